// round 12
// baseline (speedup 1.0000x reference)
#include <cuda_runtime.h>
#include <cuda_fp16.h>
#include <float.h>
#include <stdint.h>

#define NCODES   4096
#define CDIM     64
#define NTOK     65536
#define HW       4096
#define M_TILE   128
#define N_CHUNK  128
#define NCHUNKS  32
#define THREADS  256
#define SCALE    64.0f
#define EPSB     4.0f      // scaled certification gap (1e-3 descaled)

#define B_STRIDE 144      // 64 halves (128B) + 16B pad -> conflict-free ldmatrix
#define ESQ_TAIL 18432    // esq tail offset inside each BH buffer

// ---- smem byte offsets (per CTA total 109568 -> 2 CTAs/SM) ----
#define OFF_ZS     0        // 64*130*4 = 33280 fp32 z (scaled); reused as gather stage
#define OFF_BH0    33280
#define OFF_BL0    52224
#define OFF_BH1    71168
#define OFF_BL1    90112    // ends 109056
#define OFF_SIDX   109056   // 128 ints
#define SMEM_TOTAL 109568

__device__ float  g_esq[NCODES];             // scaled by 4096
__device__ __half g_embh[NCODES * CDIM];     // hi(e*64)
__device__ __half g_embl[NCODES * CDIM];     // lo(e*64)
__device__ int    g_fbcnt;
__device__ int    g_fblist[8192];

__device__ __forceinline__ uint32_t smem_u32(const void* p) {
    uint32_t a;
    asm("{ .reg .u64 t; cvta.to.shared.u64 t, %1; cvt.u32.u64 %0, t; }" : "=r"(a) : "l"(p));
    return a;
}
__device__ __forceinline__ void cp16(uint32_t dst, const void* src) {
    asm volatile("cp.async.cg.shared.global [%0], [%1], 16;" :: "r"(dst), "l"(src));
}
__device__ __forceinline__ void cp_commit() { asm volatile("cp.async.commit_group;"); }
template <int N>
__device__ __forceinline__ void cp_wait() { asm volatile("cp.async.wait_group %0;" :: "n"(N)); }

__device__ __forceinline__ void mma16816(float* c, const uint32_t* a, uint32_t b0, uint32_t b1) {
    asm volatile(
        "mma.sync.aligned.m16n8k16.row.col.f32.f16.f16.f32 "
        "{%0,%1,%2,%3}, {%4,%5,%6,%7}, {%8,%9}, {%0,%1,%2,%3};"
        : "+f"(c[0]), "+f"(c[1]), "+f"(c[2]), "+f"(c[3])
        : "r"(a[0]), "r"(a[1]), "r"(a[2]), "r"(a[3]), "r"(b0), "r"(b1));
}
__device__ __forceinline__ void mma16816h(uint32_t* c, const uint32_t* a, uint32_t b0, uint32_t b1) {
    asm volatile(
        "mma.sync.aligned.m16n8k16.row.col.f16.f16.f16.f16 "
        "{%0,%1}, {%2,%3,%4,%5}, {%6,%7}, {%0,%1};"
        : "+r"(c[0]), "+r"(c[1])
        : "r"(a[0]), "r"(a[1]), "r"(a[2]), "r"(a[3]), "r"(b0), "r"(b1));
}
__device__ __forceinline__ void ldmx4(uint32_t& r0, uint32_t& r1, uint32_t& r2, uint32_t& r3,
                                      uint32_t a) {
    asm volatile("ldmatrix.sync.aligned.m8n8.x4.shared.b16 {%0,%1,%2,%3}, [%4];"
        : "=r"(r0), "=r"(r1), "=r"(r2), "=r"(r3) : "r"(a));
}
__device__ __forceinline__ uint32_t pack2h(float v0, float v1) {
    __half h0 = __float2half_rn(v0);
    __half h1 = __float2half_rn(v1);
    return (uint32_t)__half_as_ushort(h0) | ((uint32_t)__half_as_ushort(h1) << 16);
}

__global__ void init_kernel() { g_fbcnt = 0; }

// prep: hi/lo fp16 codebook (scaled by 64) + scaled ||e||^2. one warp per code.
__global__ void prep_kernel(const float* __restrict__ emb) {
    int warp = (blockIdx.x * blockDim.x + threadIdx.x) >> 5;
    int lane = threadIdx.x & 31;
    if (warp >= NCODES) return;
    const float* row = emb + (size_t)warp * CDIM;
    float v0 = row[lane] * SCALE, v1 = row[lane + 32] * SCALE;
    __half h0 = __float2half_rn(v0), h1 = __float2half_rn(v1);
    g_embh[warp * CDIM + lane]      = h0;
    g_embh[warp * CDIM + lane + 32] = h1;
    g_embl[warp * CDIM + lane]      = __float2half_rn(v0 - __half2float(h0));
    g_embl[warp * CDIM + lane + 32] = __float2half_rn(v1 - __half2float(h1));
    float s = v0 * v0 + v1 * v1;   // scale^2 * ||e||^2
    #pragma unroll
    for (int off = 16; off; off >>= 1) s += __shfl_xor_sync(0xffffffffu, s, off);
    if (lane == 0) g_esq[warp] = s;
}

__global__ __launch_bounds__(THREADS, 2)
void vq_kernel(const float* __restrict__ z,
               const float* __restrict__ emb,
               float* __restrict__ out) {
    extern __shared__ char sm[];
    float* zs   = (float*)(sm + OFF_ZS);     // [64][130]
    int*   sidx = (int*)(sm + OFF_SIDX);     // [128]

    const uint32_t sb = smem_u32(sm);
    const int tid  = threadIdx.x;
    const int lane = tid & 31;
    const int wid  = tid >> 5;      // 0..7 : token rows wid*16 + {grp, grp+8}
    const int grp  = lane >> 2;     // 0..7
    const int tid4 = lane & 3;      // 0..3

    const int n0  = blockIdx.x * M_TILE;
    const int bb  = n0 >> 12;
    const int hw0 = n0 & (HW - 1);
    const float* zb = z + (size_t)bb * CDIM * HW + hw0;

    const uint32_t bh_off[2] = { OFF_BH0, OFF_BH1 };
    const uint32_t bl_off[2] = { OFF_BL0, OFF_BL1 };

    // ---- issue cp.async for chunk 0 (hi + lo + esq tail) ----
    {
        #pragma unroll
        for (int t = 0; t < 8; t++) {
            int item = tid + 256 * t;
            int mat  = item >> 10;              // 0: hi, 1: lo
            int row  = (item >> 3) & 127;
            int part = item & 7;
            const __half* src = (mat ? g_embl : g_embh) + row * 64 + part * 8;
            uint32_t dst = sb + (mat ? OFF_BL0 : OFF_BH0) + row * B_STRIDE + part * 16;
            cp16(dst, src);
        }
        if (tid < 32)
            cp16(sb + OFF_BH0 + ESQ_TAIL + tid * 16, g_esq + tid * 4);
        cp_commit();
    }

    // ---- stage z (scaled) ----
    #pragma unroll
    for (int t = 0; t < 32; t++) {
        int i = tid + 256 * t;
        int c = i >> 7, tok = i & 127;
        zs[c * 130 + tok] = zb[(size_t)c * HW + tok] * SCALE;
    }
    __syncthreads();

    // ---- A fragments (hi + lo) in registers: warp tile m16 ----
    uint32_t Ah[4][4], Al[4][4];
    {
        const int r0 = wid * 16 + grp;
        #pragma unroll
        for (int s = 0; s < 4; s++) {
            const int kb = 2 * tid4 + 16 * s;
            #pragma unroll
            for (int j = 0; j < 4; j++) {
                const int kk = kb + (j >> 1) * 8;
                const int rr = r0 + (j & 1) * 8;
                float v0 = zs[kk * 130 + rr];
                float v1 = zs[(kk + 1) * 130 + rr];
                __half h0 = __float2half_rn(v0), h1 = __float2half_rn(v1);
                Ah[s][j] = (uint32_t)__half_as_ushort(h0) | ((uint32_t)__half_as_ushort(h1) << 16);
                Al[s][j] = pack2h(v0 - __half2float(h0), v1 - __half2float(h1));
            }
        }
    }
    cp_wait<0>();
    __syncthreads();

    const int lrow  = (lane & 7) + ((lane >> 4) & 1) * 8;
    const int lkoff = ((lane >> 3) & 1) * 16;

    float b0v[2], b1v[2];
    int   b0i[2];
    b0v[0] = b0v[1] = FLT_MAX;
    b1v[0] = b1v[1] = FLT_MAX;
    b0i[0] = b0i[1] = 0;

    for (int ch = 0; ch < NCHUNKS; ch++) {
        const int buf = ch & 1;

        // issue next chunk into buf^1
        if (ch < NCHUNKS - 1) {
            const size_t cbase = (size_t)(ch + 1) * N_CHUNK * CDIM;
            #pragma unroll
            for (int t = 0; t < 8; t++) {
                int item = tid + 256 * t;
                int mat  = item >> 10;
                int row  = (item >> 3) & 127;
                int part = item & 7;
                const __half* src = (mat ? g_embl : g_embh) + cbase + row * 64 + part * 8;
                uint32_t dst = sb + (mat ? bl_off[buf ^ 1] : bh_off[buf ^ 1]) + row * B_STRIDE + part * 16;
                cp16(dst, src);
            }
            if (tid < 32)
                cp16(sb + bh_off[buf ^ 1] + ESQ_TAIL + tid * 16,
                     g_esq + (ch + 1) * N_CHUNK + tid * 4);
            cp_commit();
        }

        const float* esq_t = (const float*)(sm + bh_off[buf] + ESQ_TAIL);

        // ---- four n32 steps per chunk ----
        #pragma unroll
        for (int step = 0; step < 4; step++) {
            const int nbase = step * 32;
            const uint32_t bhb = sb + bh_off[buf] + (uint32_t)(nbase + lrow) * B_STRIDE + lkoff;
            const uint32_t blb = sb + bl_off[buf] + (uint32_t)(nbase + lrow) * B_STRIDE + lkoff;

            float acc[4][4];            // P1 = hi*hi, fp32 acc
            uint32_t accL[8];           // P2+P3 shared fp16 acc (4 frags x 2 regs)
            #pragma unroll
            for (int f = 0; f < 4; f++) {
                #pragma unroll
                for (int r = 0; r < 4; r++) acc[f][r] = 0.f;
                accL[2 * f] = 0u; accL[2 * f + 1] = 0u;
            }

            #pragma unroll
            for (int s = 0; s < 4; s++) {
                #pragma unroll
                for (int fp = 0; fp < 2; fp++) {
                    uint32_t h0, h1, h2, h3, L0, L1, L2, L3;
                    ldmx4(h0, h1, h2, h3, bhb + fp * (16 * B_STRIDE) + s * 32);
                    ldmx4(L0, L1, L2, L3, blb + fp * (16 * B_STRIDE) + s * 32);
                    const int f0 = 2 * fp, f1 = 2 * fp + 1;
                    mma16816(acc[f0], Ah[s], h0, h1);            // hi*hi fp32
                    mma16816(acc[f1], Ah[s], h2, h3);
                    mma16816h(&accL[2 * f0], Ah[s], L0, L1);     // hi*lo fp16
                    mma16816h(&accL[2 * f1], Ah[s], L2, L3);
                    mma16816h(&accL[2 * f0], Al[s], h0, h1);     // lo*hi fp16
                    mma16816h(&accL[2 * f1], Al[s], h2, h3);
                }
            }

            // ---- epilogue: scores, min-tree, rare best2 update ----
            const int cb = ch * N_CHUNK + nbase;
            float2 ee[4];
            #pragma unroll
            for (int f = 0; f < 4; f++)
                ee[f] = *(const float2*)&esq_t[nbase + f * 8 + 2 * tid4];

            #pragma unroll
            for (int g = 0; g < 2; g++) {   // g=0 -> row grp; g=1 -> row grp+8
                float sv[8];
                #pragma unroll
                for (int f = 0; f < 4; f++) {
                    float2 pl = __half22float2(*(const __half2*)&accL[2 * f + g]);
                    sv[2 * f]     = fmaf(acc[f][g * 2 + 0] + pl.x, -2.0f, ee[f].x);
                    sv[2 * f + 1] = fmaf(acc[f][g * 2 + 1] + pl.y, -2.0f, ee[f].y);
                }
                float m01 = fminf(sv[0], sv[1]), m23 = fminf(sv[2], sv[3]);
                float m45 = fminf(sv[4], sv[5]), m67 = fminf(sv[6], sv[7]);
                float mn = fminf(fminf(m01, m23), fminf(m45, m67));
                if (mn < b1v[g]) {
                    #pragma unroll
                    for (int j = 0; j < 8; j++) {
                        float v = sv[j];
                        if (v < b0v[g]) {
                            b1v[g] = b0v[g];
                            b0v[g] = v;
                            b0i[g] = cb + (j >> 1) * 8 + 2 * tid4 + (j & 1);
                        } else if (v < b1v[g]) {
                            b1v[g] = v;
                        }
                    }
                }
            }
        }

        cp_wait<0>();
        __syncthreads();
    }

    // ---- exact best2 merge over tid4 quad; flag uncertain tokens ----
    #pragma unroll
    for (int g = 0; g < 2; g++) {
        float v0 = b0v[g], v1 = b1v[g];
        int   i0 = b0i[g];
        #pragma unroll
        for (int off = 1; off <= 2; off <<= 1) {
            float ov0 = __shfl_xor_sync(0xffffffffu, v0, off);
            float ov1 = __shfl_xor_sync(0xffffffffu, v1, off);
            int   oi0 = __shfl_xor_sync(0xffffffffu, i0, off);
            if (ov0 < v0 || (ov0 == v0 && oi0 < i0)) {
                v1 = fminf(v0, ov1);
                v0 = ov0; i0 = oi0;
            } else {
                v1 = fminf(v1, ov0);
            }
        }
        if (tid4 == 0) {
            int token = wid * 16 + g * 8 + grp;
            sidx[token] = i0;
            if (v1 - v0 < EPSB) {
                int p = atomicAdd(&g_fbcnt, 1);
                if (p < 8192) g_fblist[p] = n0 + token;
            }
        }
    }
    __syncthreads();

    // ---- gather emb[idx], transposed coalesced write (stage in zs region) ----
    float* st = zs;   // [128][65]
    #pragma unroll
    for (int t = 0; t < 32; t++) {
        int i = tid + 256 * t;
        int tok = i >> 6, c = i & 63;
        st[tok * 65 + c] = emb[(size_t)sidx[tok] * CDIM + c];
    }
    __syncthreads();
    float* ob = out + (size_t)bb * CDIM * HW + hw0;
    #pragma unroll
    for (int t = 0; t < 32; t++) {
        int i = tid + 256 * t;
        int c = i >> 7, tok = i & 127;
        ob[(size_t)c * HW + tok] = st[tok * 65 + c];
    }
}

// ---- fallback: exact fp32 rescan for flagged tokens ----
__global__ __launch_bounds__(256, 4)
void vq_fallback(const float* __restrict__ z,
                 const float* __restrict__ emb,
                 float* __restrict__ out) {
    __shared__ float zloc[64];
    __shared__ float rv[8];
    __shared__ int   ri[8];
    __shared__ int   bestc;

    if (blockIdx.x >= g_fbcnt) return;
    const int gtok = g_fblist[blockIdx.x];
    const int tid  = threadIdx.x;
    const int lane = tid & 31;
    const int wid  = tid >> 5;
    const int bb   = gtok >> 12;
    const int hw   = gtok & (HW - 1);
    const float* zt = z + (size_t)bb * CDIM * HW + hw;

    if (tid < 64) zloc[tid] = zt[(size_t)tid * HW];
    __syncthreads();

    float bv = FLT_MAX; int bi = 0;
    for (int c = tid; c < NCODES; c += 256) {
        const float4* e4 = (const float4*)(emb + (size_t)c * CDIM);
        float dot = 0.f;
        #pragma unroll
        for (int k4 = 0; k4 < 16; k4++) {
            float4 e = __ldg(&e4[k4]);
            dot = fmaf(zloc[4 * k4 + 0], e.x, dot);
            dot = fmaf(zloc[4 * k4 + 1], e.y, dot);
            dot = fmaf(zloc[4 * k4 + 2], e.z, dot);
            dot = fmaf(zloc[4 * k4 + 3], e.w, dot);
        }
        float d = g_esq[c] - 8192.0f * dot;   // g_esq scaled by 4096
        if (d < bv || (d == bv && c < bi)) { bv = d; bi = c; }
    }
    #pragma unroll
    for (int off = 16; off; off >>= 1) {
        float ov = __shfl_xor_sync(0xffffffffu, bv, off);
        int   oi = __shfl_xor_sync(0xffffffffu, bi, off);
        if (ov < bv || (ov == bv && oi < bi)) { bv = ov; bi = oi; }
    }
    if (lane == 0) { rv[wid] = bv; ri[wid] = bi; }
    __syncthreads();
    if (tid == 0) {
        float fv = rv[0]; int fi = ri[0];
        #pragma unroll
        for (int w = 1; w < 8; w++)
            if (rv[w] < fv || (rv[w] == fv && ri[w] < fi)) { fv = rv[w]; fi = ri[w]; }
        bestc = fi;
    }
    __syncthreads();
    if (tid < 64)
        out[(size_t)bb * CDIM * HW + (size_t)tid * HW + hw] = emb[(size_t)bestc * CDIM + tid];
}

extern "C" void kernel_launch(void* const* d_in, const int* in_sizes, int n_in,
                              void* d_out, int out_size) {
    const float* z   = (const float*)d_in[0];
    const float* emb = (const float*)d_in[1];
    float* out = (float*)d_out;

    cudaFuncSetAttribute(vq_kernel, cudaFuncAttributeMaxDynamicSharedMemorySize, SMEM_TOTAL);

    init_kernel<<<1, 1>>>();
    prep_kernel<<<NCODES / 8, 256>>>(emb);
    vq_kernel<<<NTOK / M_TILE, THREADS, SMEM_TOTAL>>>(z, emb, out);
    vq_fallback<<<1024, 256>>>(z, emb, out);
}

// round 13
// speedup vs baseline: 1.3712x; 1.3712x over previous
#include <cuda_runtime.h>
#include <cuda_fp16.h>
#include <float.h>
#include <stdint.h>

#define NCODES   4096
#define CDIM     64
#define NTOK     65536
#define HW       4096
#define M_TILE   128
#define N_CHUNK  64
#define NCHUNKS  64
#define THREADS  256
#define SCALE    64.0f

#define B_STRIDE 144      // 64 halves (128B) + 16B pad -> conflict-free ldmatrix
#define ESQ_TAIL 9216     // esq tail offset inside each BH buffer

// ---- smem byte offsets (per CTA total 74752 -> 3 CTAs/SM) ----
#define OFF_AH     0        // 128*144 fp16 z-hi tile (reused as gather stage)
#define OFF_AL     18432    // 128*144 fp16 z-lo tile
#define OFF_BH0    36864    // 9216 data + 256 esq tail
#define OFF_BL0    46336    // 9216
#define OFF_BH1    55552    // 9216 + 256
#define OFF_BL1    65024    // 9216 (ends 74240)
#define OFF_SIDX   74240    // 128 ints
#define SMEM_TOTAL 74752

__device__ float  g_esq[NCODES];             // scaled by 4096
__device__ __half g_embh[NCODES * CDIM];     // hi(e*64)
__device__ __half g_embl[NCODES * CDIM];     // lo(e*64)

__device__ __forceinline__ uint32_t smem_u32(const void* p) {
    uint32_t a;
    asm("{ .reg .u64 t; cvta.to.shared.u64 t, %1; cvt.u32.u64 %0, t; }" : "=r"(a) : "l"(p));
    return a;
}
__device__ __forceinline__ void cp16(uint32_t dst, const void* src) {
    asm volatile("cp.async.cg.shared.global [%0], [%1], 16;" :: "r"(dst), "l"(src));
}
__device__ __forceinline__ void cp_commit() { asm volatile("cp.async.commit_group;"); }
template <int N>
__device__ __forceinline__ void cp_wait() { asm volatile("cp.async.wait_group %0;" :: "n"(N)); }

__device__ __forceinline__ void mma16816(float* c, const uint32_t* a, uint32_t b0, uint32_t b1) {
    asm volatile(
        "mma.sync.aligned.m16n8k16.row.col.f32.f16.f16.f32 "
        "{%0,%1,%2,%3}, {%4,%5,%6,%7}, {%8,%9}, {%0,%1,%2,%3};"
        : "+f"(c[0]), "+f"(c[1]), "+f"(c[2]), "+f"(c[3])
        : "r"(a[0]), "r"(a[1]), "r"(a[2]), "r"(a[3]), "r"(b0), "r"(b1));
}
__device__ __forceinline__ void ldmx4(uint32_t& r0, uint32_t& r1, uint32_t& r2, uint32_t& r3,
                                      uint32_t a) {
    asm volatile("ldmatrix.sync.aligned.m8n8.x4.shared.b16 {%0,%1,%2,%3}, [%4];"
        : "=r"(r0), "=r"(r1), "=r"(r2), "=r"(r3) : "r"(a));
}
__device__ __forceinline__ uint32_t pack2h(float v0, float v1) {
    __half h0 = __float2half_rn(v0);
    __half h1 = __float2half_rn(v1);
    return (uint32_t)__half_as_ushort(h0) | ((uint32_t)__half_as_ushort(h1) << 16);
}

// prep: hi/lo fp16 codebook (scaled by 64) + scaled ||e||^2. one warp per code.
__global__ void prep_kernel(const float* __restrict__ emb) {
    int warp = (blockIdx.x * blockDim.x + threadIdx.x) >> 5;
    int lane = threadIdx.x & 31;
    if (warp >= NCODES) return;
    const float* row = emb + (size_t)warp * CDIM;
    float v0 = row[lane] * SCALE, v1 = row[lane + 32] * SCALE;
    __half h0 = __float2half_rn(v0), h1 = __float2half_rn(v1);
    g_embh[warp * CDIM + lane]      = h0;
    g_embh[warp * CDIM + lane + 32] = h1;
    g_embl[warp * CDIM + lane]      = __float2half_rn(v0 - __half2float(h0));
    g_embl[warp * CDIM + lane + 32] = __float2half_rn(v1 - __half2float(h1));
    float s = v0 * v0 + v1 * v1;   // scale^2 * ||e||^2
    #pragma unroll
    for (int off = 16; off; off >>= 1) s += __shfl_xor_sync(0xffffffffu, s, off);
    if (lane == 0) g_esq[warp] = s;
}

__global__ __launch_bounds__(THREADS, 3)
void vq_kernel(const float* __restrict__ z,
               const float* __restrict__ emb,
               float* __restrict__ out) {
    extern __shared__ char sm[];
    int* sidx = (int*)(sm + OFF_SIDX);       // [128]

    const uint32_t sb = smem_u32(sm);
    const int tid  = threadIdx.x;
    const int lane = tid & 31;
    const int wid  = tid >> 5;      // 0..7 : token rows wid*16 + {grp, grp+8}
    const int grp  = lane >> 2;     // 0..7
    const int tid4 = lane & 3;      // 0..3

    const int n0  = blockIdx.x * M_TILE;
    const int bb  = n0 >> 12;
    const int hw0 = n0 & (HW - 1);
    const float* zb = z + (size_t)bb * CDIM * HW + hw0;

    const uint32_t bh_off[2] = { OFF_BH0, OFF_BH1 };
    const uint32_t bl_off[2] = { OFF_BL0, OFF_BL1 };

    // ---- issue cp.async for chunk 0 (hi + lo + esq tail) ----
    {
        #pragma unroll
        for (int t = 0; t < 4; t++) {
            int item = tid + 256 * t;          // 0..1023
            int mat  = item >> 9;              // 0: hi, 1: lo
            int row  = (item >> 3) & 63;
            int part = item & 7;
            const __half* src = (mat ? g_embl : g_embh) + row * 64 + part * 8;
            uint32_t dst = sb + (mat ? OFF_BL0 : OFF_BH0) + row * B_STRIDE + part * 16;
            cp16(dst, src);
        }
        if (tid < 16)
            cp16(sb + OFF_BH0 + ESQ_TAIL + tid * 16, g_esq + tid * 4);
        cp_commit();
    }

    // ---- stage z as fp16 hi/lo tiles (scaled): row = token ----
    #pragma unroll
    for (int t = 0; t < 16; t++) {
        int i   = tid + 256 * t;           // 0..4095 over (c-pair, token)
        int c2  = (i >> 7) * 2;
        int tok = i & 127;
        float v0 = zb[(size_t)c2 * HW + tok] * SCALE;
        float v1 = zb[(size_t)(c2 + 1) * HW + tok] * SCALE;
        __half h0 = __float2half_rn(v0), h1 = __float2half_rn(v1);
        uint32_t hi = (uint32_t)__half_as_ushort(h0) | ((uint32_t)__half_as_ushort(h1) << 16);
        uint32_t lo = pack2h(v0 - __half2float(h0), v1 - __half2float(h1));
        *(uint32_t*)(sm + OFF_AH + tok * B_STRIDE + c2 * 2) = hi;
        *(uint32_t*)(sm + OFF_AL + tok * B_STRIDE + c2 * 2) = lo;
    }
    cp_wait<0>();
    __syncthreads();

    // ldmatrix lane address pieces
    const int arow  = (lane & 7) + ((lane >> 3) & 1) * 8;   // A operand pattern
    const int akoff = ((lane >> 4) & 1) * 16;
    const int brow  = (lane & 7) + ((lane >> 4) & 1) * 8;   // B operand pattern
    const int bkoff = ((lane >> 3) & 1) * 16;

    const uint32_t ahad = sb + OFF_AH + (uint32_t)(wid * 16 + arow) * B_STRIDE + akoff;
    const uint32_t alad = sb + OFF_AL + (uint32_t)(wid * 16 + arow) * B_STRIDE + akoff;

    float best[2];
    int   bidx[2];
    best[0] = best[1] = FLT_MAX;
    bidx[0] = bidx[1] = 0;

    for (int ch = 0; ch < NCHUNKS; ch++) {
        const int buf = ch & 1;

        // issue next chunk into buf^1
        if (ch < NCHUNKS - 1) {
            const size_t cbase = (size_t)(ch + 1) * N_CHUNK * CDIM;
            #pragma unroll
            for (int t = 0; t < 4; t++) {
                int item = tid + 256 * t;
                int mat  = item >> 9;
                int row  = (item >> 3) & 63;
                int part = item & 7;
                const __half* src = (mat ? g_embl : g_embh) + cbase + row * 64 + part * 8;
                uint32_t dst = sb + (mat ? bl_off[buf ^ 1] : bh_off[buf ^ 1]) + row * B_STRIDE + part * 16;
                cp16(dst, src);
            }
            if (tid < 16)
                cp16(sb + bh_off[buf ^ 1] + ESQ_TAIL + tid * 16,
                     g_esq + (ch + 1) * N_CHUNK + tid * 4);
            cp_commit();
        }

        const float* esq_t = (const float*)(sm + bh_off[buf] + ESQ_TAIL);

        // ---- two n32 steps over the 64-code chunk ----
        #pragma unroll
        for (int step = 0; step < 2; step++) {
            const int nbase = step * 32;
            const uint32_t bhb = sb + bh_off[buf] + (uint32_t)(nbase + brow) * B_STRIDE + bkoff;
            const uint32_t blb = sb + bl_off[buf] + (uint32_t)(nbase + brow) * B_STRIDE + bkoff;

            float acc[4][4];
            #pragma unroll
            for (int f = 0; f < 4; f++)
                #pragma unroll
                for (int r = 0; r < 4; r++) acc[f][r] = 0.f;

            #pragma unroll
            for (int s = 0; s < 4; s++) {
                uint32_t ah[4], al[4];
                ldmx4(ah[0], ah[1], ah[2], ah[3], ahad + s * 32);
                ldmx4(al[0], al[1], al[2], al[3], alad + s * 32);
                #pragma unroll
                for (int fp = 0; fp < 2; fp++) {
                    uint32_t h0, h1, h2, h3, L0, L1, L2, L3;
                    ldmx4(h0, h1, h2, h3, bhb + fp * (16 * B_STRIDE) + s * 32);
                    ldmx4(L0, L1, L2, L3, blb + fp * (16 * B_STRIDE) + s * 32);
                    const int f0 = 2 * fp, f1 = 2 * fp + 1;
                    mma16816(acc[f0], ah, h0, h1);   // hi*hi
                    mma16816(acc[f1], ah, h2, h3);
                    mma16816(acc[f0], ah, L0, L1);   // hi*lo
                    mma16816(acc[f1], ah, L2, L3);
                    mma16816(acc[f0], al, h0, h1);   // lo*hi
                    mma16816(acc[f1], al, h2, h3);
                }
            }

            // ---- epilogue: min-tree + rare rescan (exact, first-min tiebreak) ----
            const int cb = ch * N_CHUNK + nbase;
            float2 ee[4];
            #pragma unroll
            for (int f = 0; f < 4; f++)
                ee[f] = *(const float2*)&esq_t[nbase + f * 8 + 2 * tid4];

            #pragma unroll
            for (int g = 0; g < 2; g++) {   // g=0 -> row grp; g=1 -> row grp+8
                float sv[8];
                #pragma unroll
                for (int f = 0; f < 4; f++) {
                    sv[2 * f]     = fmaf(acc[f][g * 2 + 0], -2.0f, ee[f].x);
                    sv[2 * f + 1] = fmaf(acc[f][g * 2 + 1], -2.0f, ee[f].y);
                }
                float m01 = fminf(sv[0], sv[1]), m23 = fminf(sv[2], sv[3]);
                float m45 = fminf(sv[4], sv[5]), m67 = fminf(sv[6], sv[7]);
                float mn = fminf(fminf(m01, m23), fminf(m45, m67));
                if (mn < best[g]) {
                    best[g] = mn;
                    int found = -1;
                    #pragma unroll
                    for (int j = 0; j < 8; j++)
                        if (found < 0 && sv[j] == mn)
                            found = cb + (j >> 1) * 8 + 2 * tid4 + (j & 1);
                    bidx[g] = found;
                }
            }
        }

        cp_wait<0>();
        __syncthreads();
    }

    // ---- reduce over tid4 quad (codes); each warp owns its tokens ----
    #pragma unroll
    for (int g = 0; g < 2; g++) {
        float v  = best[g];
        int   id = bidx[g];
        #pragma unroll
        for (int off = 1; off <= 2; off <<= 1) {
            float ov = __shfl_xor_sync(0xffffffffu, v, off);
            int   oi = __shfl_xor_sync(0xffffffffu, id, off);
            if (ov < v || (ov == v && oi < id)) { v = ov; id = oi; }
        }
        if (tid4 == 0)
            sidx[wid * 16 + g * 8 + grp] = id;
    }
    __syncthreads();

    // ---- gather emb[idx], transposed coalesced write (stage over A tiles) ----
    float* st = (float*)(sm + OFF_AH);   // [128][65] = 33280 B < 36864 B
    #pragma unroll
    for (int t = 0; t < 32; t++) {
        int i = tid + 256 * t;
        int tok = i >> 6, c = i & 63;
        st[tok * 65 + c] = emb[(size_t)sidx[tok] * CDIM + c];
    }
    __syncthreads();
    float* ob = out + (size_t)bb * CDIM * HW + hw0;
    #pragma unroll
    for (int t = 0; t < 32; t++) {
        int i = tid + 256 * t;
        int c = i >> 7, tok = i & 127;
        ob[(size_t)c * HW + tok] = st[tok * 65 + c];
    }
}

extern "C" void kernel_launch(void* const* d_in, const int* in_sizes, int n_in,
                              void* d_out, int out_size) {
    const float* z   = (const float*)d_in[0];
    const float* emb = (const float*)d_in[1];
    float* out = (float*)d_out;

    cudaFuncSetAttribute(vq_kernel, cudaFuncAttributeMaxDynamicSharedMemorySize, SMEM_TOTAL);

    prep_kernel<<<NCODES / 8, 256>>>(emb);
    vq_kernel<<<NTOK / M_TILE, THREADS, SMEM_TOTAL>>>(z, emb, out);
}

// round 14
// speedup vs baseline: 1.6835x; 1.2278x over previous
#include <cuda_runtime.h>
#include <cuda_fp16.h>
#include <float.h>
#include <stdint.h>

#define NCODES   4096
#define CDIM     64
#define NTOK     65536
#define HW       4096
#define M_TILE   128
#define N_CHUNK  64
#define NCHUNKS  64
#define THREADS  256
#define SCALE    64.0f
#define DESC     2.44140625e-4f   // 1/4096

#define B_STRIDE 144      // 64 halves (128B) + 16B pad -> conflict-free ldmatrix
#define ESQ_TAIL 9216     // esq tail offset inside each BH buffer

// ---- main kernel smem (per CTA 47616 -> 3 CTAs/SM) ----
#define OFF_AH     0        // 128*144 fp16 z-hi tile
#define OFF_BH0    18432    // 9216 + 256 esq
#define OFF_BH1    27904    // 9216 + 256 esq
#define OFF_SB     37376    // submin transpose buf: 128 tok x 40 halves = 10240
#define SMEM_MAIN  47616

// ---- resolve kernel smem ----
#define SMEM_RES   33792    // zs[64*130]f (reused as gather stage) + sidx[128]

__device__ float  g_esq[NCODES];               // ||e*64||^2 (scaled by 4096)
__device__ __half g_embh[NCODES * CDIM];       // hi(e*64)
__device__ __half g_smin[(size_t)NTOK * 512];  // per (token, 8-code group) min, descaled
__device__ int    g_Eh2 = 0;                   // max_c ||hi_e||^2 (scaled), float bits
__device__ int    g_El2 = 0;                   // max_c ||lo_e||^2 (scaled), float bits

__device__ __forceinline__ uint32_t smem_u32(const void* p) {
    uint32_t a;
    asm("{ .reg .u64 t; cvta.to.shared.u64 t, %1; cvt.u32.u64 %0, t; }" : "=r"(a) : "l"(p));
    return a;
}
__device__ __forceinline__ void cp16(uint32_t dst, const void* src) {
    asm volatile("cp.async.cg.shared.global [%0], [%1], 16;" :: "r"(dst), "l"(src));
}
__device__ __forceinline__ void cp_commit() { asm volatile("cp.async.commit_group;"); }
template <int N>
__device__ __forceinline__ void cp_wait() { asm volatile("cp.async.wait_group %0;" :: "n"(N)); }

__device__ __forceinline__ void mma16816(float* c, const uint32_t* a, uint32_t b0, uint32_t b1) {
    asm volatile(
        "mma.sync.aligned.m16n8k16.row.col.f32.f16.f16.f32 "
        "{%0,%1,%2,%3}, {%4,%5,%6,%7}, {%8,%9}, {%0,%1,%2,%3};"
        : "+f"(c[0]), "+f"(c[1]), "+f"(c[2]), "+f"(c[3])
        : "r"(a[0]), "r"(a[1]), "r"(a[2]), "r"(a[3]), "r"(b0), "r"(b1));
}
__device__ __forceinline__ void ldmx4(uint32_t& r0, uint32_t& r1, uint32_t& r2, uint32_t& r3,
                                      uint32_t a) {
    asm volatile("ldmatrix.sync.aligned.m8n8.x4.shared.b16 {%0,%1,%2,%3}, [%4];"
        : "=r"(r0), "=r"(r1), "=r"(r2), "=r"(r3) : "r"(a));
}
__device__ __forceinline__ uint32_t pack2h(float v0, float v1) {
    __half h0 = __float2half_rn(v0);
    __half h1 = __float2half_rn(v1);
    return (uint32_t)__half_as_ushort(h0) | ((uint32_t)__half_as_ushort(h1) << 16);
}

// prep: hi fp16 codebook (scaled), esq, max hi/lo norms. one warp per code.
__global__ void prep_kernel(const float* __restrict__ emb) {
    int warp = (blockIdx.x * blockDim.x + threadIdx.x) >> 5;
    int lane = threadIdx.x & 31;
    if (warp >= NCODES) return;
    const float* row = emb + (size_t)warp * CDIM;
    float v0 = row[lane] * SCALE, v1 = row[lane + 32] * SCALE;
    __half h0 = __float2half_rn(v0), h1 = __float2half_rn(v1);
    g_embh[warp * CDIM + lane]      = h0;
    g_embh[warp * CDIM + lane + 32] = h1;
    float hf0 = __half2float(h0), hf1 = __half2float(h1);
    float l0 = v0 - hf0, l1 = v1 - hf1;
    float s  = v0 * v0 + v1 * v1;
    float hs = hf0 * hf0 + hf1 * hf1;
    float ls = l0 * l0 + l1 * l1;
    #pragma unroll
    for (int off = 16; off; off >>= 1) {
        s  += __shfl_xor_sync(0xffffffffu, s,  off);
        hs += __shfl_xor_sync(0xffffffffu, hs, off);
        ls += __shfl_xor_sync(0xffffffffu, ls, off);
    }
    if (lane == 0) {
        g_esq[warp] = s;
        atomicMax(&g_Eh2, __float_as_int(hs));   // positive floats: int order = float order
        atomicMax(&g_El2, __float_as_int(ls));
    }
}

// ---- stage 1: 1-pass hi*hi GEMM, per-group min -> g_smin ----
__global__ __launch_bounds__(THREADS, 3)
void vq_main(const float* __restrict__ z) {
    extern __shared__ char sm[];
    const uint32_t sb = smem_u32(sm);
    const int tid  = threadIdx.x;
    const int lane = tid & 31;
    const int wid  = tid >> 5;      // 0..7 : token rows wid*16 + {grp, grp+8}
    const int grp  = lane >> 2;
    const int tid4 = lane & 3;

    const int n0  = blockIdx.x * M_TILE;
    const int bb  = n0 >> 12;
    const int hw0 = n0 & (HW - 1);
    const float* zb = z + (size_t)bb * CDIM * HW + hw0;

    const uint32_t bh_off[2] = { OFF_BH0, OFF_BH1 };

    // prologue: cp.async chunk 0 (hi + esq tail)
    {
        #pragma unroll
        for (int t = 0; t < 2; t++) {
            int item = tid + 256 * t;          // 0..511
            int row  = item >> 3;
            int part = item & 7;
            cp16(sb + OFF_BH0 + row * B_STRIDE + part * 16, g_embh + row * 64 + part * 8);
        }
        if (tid < 16)
            cp16(sb + OFF_BH0 + ESQ_TAIL + tid * 16, g_esq + tid * 4);
        cp_commit();
    }

    // stage z (scaled, hi only) into A tile
    #pragma unroll
    for (int t = 0; t < 16; t++) {
        int i   = tid + 256 * t;
        int c2  = (i >> 7) * 2;
        int tok = i & 127;
        float v0 = zb[(size_t)c2 * HW + tok] * SCALE;
        float v1 = zb[(size_t)(c2 + 1) * HW + tok] * SCALE;
        *(uint32_t*)(sm + OFF_AH + tok * B_STRIDE + c2 * 2) = pack2h(v0, v1);
    }
    cp_wait<0>();
    __syncthreads();

    // ldmatrix lane address pieces (R13 mapping)
    const int arow  = (lane & 7) + ((lane >> 3) & 1) * 8;
    const int akoff = ((lane >> 4) & 1) * 16;
    const int brow  = (lane & 7) + ((lane >> 4) & 1) * 8;
    const int bkoff = ((lane >> 3) & 1) * 16;

    // A fragments persistent in registers (chunk-invariant)
    uint32_t Ah[4][4];
    {
        const uint32_t ahad = sb + OFF_AH + (uint32_t)(wid * 16 + arow) * B_STRIDE + akoff;
        #pragma unroll
        for (int s = 0; s < 4; s++)
            ldmx4(Ah[s][0], Ah[s][1], Ah[s][2], Ah[s][3], ahad + s * 32);
    }

    for (int ch = 0; ch < NCHUNKS; ch++) {
        const int buf = ch & 1;

        if (ch < NCHUNKS - 1) {
            const size_t cbase = (size_t)(ch + 1) * N_CHUNK * CDIM;
            #pragma unroll
            for (int t = 0; t < 2; t++) {
                int item = tid + 256 * t;
                int row  = item >> 3;
                int part = item & 7;
                cp16(sb + bh_off[buf ^ 1] + row * B_STRIDE + part * 16,
                     g_embh + cbase + row * 64 + part * 8);
            }
            if (tid < 16)
                cp16(sb + bh_off[buf ^ 1] + ESQ_TAIL + tid * 16,
                     g_esq + (ch + 1) * N_CHUNK + tid * 4);
            cp_commit();
            cp_wait<1>();
        } else {
            cp_wait<0>();
        }
        __syncthreads();

        const float* esq_t = (const float*)(sm + bh_off[buf] + ESQ_TAIL);

        #pragma unroll
        for (int step = 0; step < 2; step++) {
            const int nbase = step * 32;
            const uint32_t bhb = sb + bh_off[buf] + (uint32_t)(nbase + brow) * B_STRIDE + bkoff;

            float acc[4][4];
            #pragma unroll
            for (int f = 0; f < 4; f++)
                #pragma unroll
                for (int r = 0; r < 4; r++) acc[f][r] = 0.f;

            #pragma unroll
            for (int s = 0; s < 4; s++) {
                #pragma unroll
                for (int fp = 0; fp < 2; fp++) {
                    uint32_t h0, h1, h2, h3;
                    ldmx4(h0, h1, h2, h3, bhb + fp * (16 * B_STRIDE) + s * 32);
                    mma16816(acc[2 * fp],     Ah[s], h0, h1);
                    mma16816(acc[2 * fp + 1], Ah[s], h2, h3);
                }
            }

            // epilogue: 8-code group min -> smem submin buffer (descaled fp16)
            float2 ee[4];
            #pragma unroll
            for (int f = 0; f < 4; f++)
                ee[f] = *(const float2*)&esq_t[nbase + f * 8 + 2 * tid4];

            const int col = ((ch & 3) * 2 + step) * 4 + tid4;
            #pragma unroll
            for (int g = 0; g < 2; g++) {
                float sv[8];
                #pragma unroll
                for (int f = 0; f < 4; f++) {
                    sv[2 * f]     = fmaf(acc[f][g * 2 + 0], -2.0f, ee[f].x);
                    sv[2 * f + 1] = fmaf(acc[f][g * 2 + 1], -2.0f, ee[f].y);
                }
                float m01 = fminf(sv[0], sv[1]), m23 = fminf(sv[2], sv[3]);
                float m45 = fminf(sv[4], sv[5]), m67 = fminf(sv[6], sv[7]);
                float mn = fminf(fminf(m01, m23), fminf(m45, m67));
                int tok = wid * 16 + g * 8 + grp;
                *(__half*)(sm + OFF_SB + tok * 80 + col * 2) = __float2half_rn(mn * DESC);
            }
        }
        __syncthreads();

        if ((ch & 3) == 3) {
            // dump 32 gids x 128 tokens to gmem, coalesced
            int tok = tid >> 1, hf = tid & 1;
            uint4 x0 = *(const uint4*)(sm + OFF_SB + tok * 80 + hf * 32);
            uint4 x1 = *(const uint4*)(sm + OFF_SB + tok * 80 + hf * 32 + 16);
            int base = (ch - 3) * 8;
            uint4* dp = (uint4*)(g_smin + (size_t)(n0 + tok) * 512 + base + hf * 16);
            dp[0] = x0;
            dp[1] = x1;
            __syncthreads();
        }
    }
}

// ---- stage 2: certified resolve + exact rescore + gather ----
__global__ __launch_bounds__(THREADS, 3)
void vq_resolve(const float* __restrict__ z,
                const float* __restrict__ emb,
                float* __restrict__ out) {
    extern __shared__ char sm[];
    float* zs   = (float*)sm;               // [64][130] natural z
    int*   sidx = (int*)(sm + 33280);       // [128]

    const int tid  = threadIdx.x;
    const int lane = tid & 31;
    const int wid  = tid >> 5;

    const int n0  = blockIdx.x * M_TILE;
    const int bb  = n0 >> 12;
    const int hw0 = n0 & (HW - 1);
    const float* zb = z + (size_t)bb * CDIM * HW + hw0;

    #pragma unroll
    for (int t = 0; t < 32; t++) {
        int i = tid + 256 * t;
        int c = i >> 7, tok = i & 127;
        zs[c * 130 + tok] = zb[(size_t)c * HW + tok];
    }
    __syncthreads();

    const float Eh2 = __int_as_float(g_Eh2);
    const float El2 = __int_as_float(g_El2);

    for (int tt = 0; tt < 16; tt++) {
        const int t  = wid * 16 + tt;
        const int tg = n0 + t;

        // load this token's 512 group mins (32B per lane)
        const uint4* sp = (const uint4*)(g_smin + (size_t)tg * 512);
        uint4 a = sp[lane * 2], b = sp[lane * 2 + 1];
        float hv[16];
        {
            uint32_t w[8] = { a.x, a.y, a.z, a.w, b.x, b.y, b.z, b.w };
            #pragma unroll
            for (int j = 0; j < 8; j++) {
                float2 f = __half22float2(*(__half2*)&w[j]);
                hv[2 * j] = f.x; hv[2 * j + 1] = f.y;
            }
        }
        float m = hv[0];
        #pragma unroll
        for (int j = 1; j < 16; j++) m = fminf(m, hv[j]);
        #pragma unroll
        for (int off = 16; off; off >>= 1)
            m = fminf(m, __shfl_xor_sync(0xffffffffu, m, off));

        // per-token error bound (scaled hi/lo norms of z)
        float hz, lz;
        {
            int c0 = 2 * lane;
            float v0 = zs[c0 * 130 + t] * SCALE;
            float v1 = zs[(c0 + 1) * 130 + t] * SCALE;
            float hf0 = __half2float(__float2half_rn(v0));
            float hf1 = __half2float(__float2half_rn(v1));
            float l0 = v0 - hf0, l1 = v1 - hf1;
            hz = hf0 * hf0 + hf1 * hf1;
            lz = l0 * l0 + l1 * l1;
            #pragma unroll
            for (int off = 16; off; off >>= 1) {
                hz += __shfl_xor_sync(0xffffffffu, hz, off);
                lz += __shfl_xor_sync(0xffffffffu, lz, off);
            }
        }
        float eps_dot = sqrtf(lz * Eh2) + sqrtf(hz * El2) + sqrtf(lz * El2);
        float thr = m + eps_dot * (4.0f * DESC) + 1.0f;   // 2*eps_dist + generous slack

        float bv = FLT_MAX;
        int   bc = 0x7fffffff;
        const int kq = lane & 3;
        const int fsel = ((lane >> 3) << 3) + ((lane >> 2) & 1);  // f*8 + p

        #pragma unroll
        for (int i = 0; i < 16; i++) {
            unsigned mb = __ballot_sync(0xffffffffu, hv[i] <= thr);
            while (mb) {
                int src = __ffs(mb) - 1;
                mb &= mb - 1;
                int gid  = src * 16 + i;
                int code = (gid >> 2) * 32 + fsel + 2 * (gid & 3);
                // exact fp32 rescore: lane dots 16 dims
                const float4* e4 = (const float4*)(emb + (size_t)code * CDIM) + kq * 4;
                float dot = 0.f;
                #pragma unroll
                for (int j = 0; j < 4; j++) {
                    float4 e = __ldg(&e4[j]);
                    int k = kq * 16 + j * 4;
                    dot = fmaf(zs[(k + 0) * 130 + t], e.x, dot);
                    dot = fmaf(zs[(k + 1) * 130 + t], e.y, dot);
                    dot = fmaf(zs[(k + 2) * 130 + t], e.z, dot);
                    dot = fmaf(zs[(k + 3) * 130 + t], e.w, dot);
                }
                dot += __shfl_xor_sync(0xffffffffu, dot, 1);
                dot += __shfl_xor_sync(0xffffffffu, dot, 2);
                float d = fmaf(dot, -2.0f, g_esq[code] * DESC);
                int   c = code;
                #pragma unroll
                for (int off = 4; off <= 16; off <<= 1) {
                    float od = __shfl_xor_sync(0xffffffffu, d, off);
                    int   oc = __shfl_xor_sync(0xffffffffu, c, off);
                    if (od < d || (od == d && oc < c)) { d = od; c = oc; }
                }
                if (d < bv || (d == bv && c < bc)) { bv = d; bc = c; }
            }
        }
        if (lane == 0) sidx[t] = bc;
    }
    __syncthreads();

    // gather emb[idx], transposed coalesced write (stage over zs)
    float* st = zs;   // [128][65] = 33280 B, exact fit
    #pragma unroll
    for (int t = 0; t < 32; t++) {
        int i = tid + 256 * t;
        int tok = i >> 6, c = i & 63;
        st[tok * 65 + c] = emb[(size_t)sidx[tok] * CDIM + c];
    }
    __syncthreads();
    float* ob = out + (size_t)bb * CDIM * HW + hw0;
    #pragma unroll
    for (int t = 0; t < 32; t++) {
        int i = tid + 256 * t;
        int c = i >> 7, tok = i & 127;
        ob[(size_t)c * HW + tok] = st[tok * 65 + c];
    }
}

extern "C" void kernel_launch(void* const* d_in, const int* in_sizes, int n_in,
                              void* d_out, int out_size) {
    const float* z   = (const float*)d_in[0];
    const float* emb = (const float*)d_in[1];
    float* out = (float*)d_out;

    cudaFuncSetAttribute(vq_main, cudaFuncAttributeMaxDynamicSharedMemorySize, SMEM_MAIN);
    cudaFuncSetAttribute(vq_resolve, cudaFuncAttributeMaxDynamicSharedMemorySize, SMEM_RES);

    prep_kernel<<<NCODES / 8, 256>>>(emb);
    vq_main<<<NTOK / M_TILE, THREADS, SMEM_MAIN>>>(z);
    vq_resolve<<<NTOK / M_TILE, THREADS, SMEM_RES>>>(z, emb, out);
}

// round 15
// speedup vs baseline: 1.8229x; 1.0828x over previous
#include <cuda_runtime.h>
#include <cuda_fp16.h>
#include <float.h>
#include <stdint.h>

#define NCODES   4096
#define CDIM     64
#define NTOK     65536
#define HW       4096
#define M_TILE   128
#define N_CHUNK  128
#define NCHUNKS  32
#define THREADS  256
#define SCALE    64.0f
#define DESC     2.44140625e-4f   // 1/4096

#define B_STRIDE 144      // 64 halves (128B) + 16B pad -> conflict-free ldmatrix
#define ESQ_TAIL 18432    // esq tail offset inside each BH buffer (128 floats)

// ---- main kernel smem (per CTA 66560 -> 3 CTAs/SM) ----
#define OFF_AH     0        // 128*144 fp16 z-hi tile
#define OFF_BH0    18432    // 18432 data + 512 esq
#define OFF_BH1    37376    // 18432 data + 512 esq
#define OFF_SB     56320    // submin transpose buf: 128 tok x 40 halves = 10240
#define SMEM_MAIN  66560

// ---- resolve kernel smem ----
#define SMEM_RES   34304    // zs[64*130]f + sidx[128] + eps[128]

__device__ float  g_esq[NCODES];               // ||e*64||^2 (scaled by 4096)
__device__ __half g_embh[NCODES * CDIM];       // hi(e*64)
__device__ __half g_smin[(size_t)NTOK * 512];  // per (token, 8-code group) min, descaled
__device__ int    g_Eh2 = 0;                   // max_c ||hi_e||^2 (scaled), float bits
__device__ int    g_El2 = 0;                   // max_c ||lo_e||^2 (scaled), float bits

__device__ __forceinline__ uint32_t smem_u32(const void* p) {
    uint32_t a;
    asm("{ .reg .u64 t; cvta.to.shared.u64 t, %1; cvt.u32.u64 %0, t; }" : "=r"(a) : "l"(p));
    return a;
}
__device__ __forceinline__ void cp16(uint32_t dst, const void* src) {
    asm volatile("cp.async.cg.shared.global [%0], [%1], 16;" :: "r"(dst), "l"(src));
}
__device__ __forceinline__ void cp_commit() { asm volatile("cp.async.commit_group;"); }
template <int N>
__device__ __forceinline__ void cp_wait() { asm volatile("cp.async.wait_group %0;" :: "n"(N)); }

__device__ __forceinline__ void mma16816(float* c, const uint32_t* a, uint32_t b0, uint32_t b1) {
    asm volatile(
        "mma.sync.aligned.m16n8k16.row.col.f32.f16.f16.f32 "
        "{%0,%1,%2,%3}, {%4,%5,%6,%7}, {%8,%9}, {%0,%1,%2,%3};"
        : "+f"(c[0]), "+f"(c[1]), "+f"(c[2]), "+f"(c[3])
        : "r"(a[0]), "r"(a[1]), "r"(a[2]), "r"(a[3]), "r"(b0), "r"(b1));
}
__device__ __forceinline__ void ldmx4(uint32_t& r0, uint32_t& r1, uint32_t& r2, uint32_t& r3,
                                      uint32_t a) {
    asm volatile("ldmatrix.sync.aligned.m8n8.x4.shared.b16 {%0,%1,%2,%3}, [%4];"
        : "=r"(r0), "=r"(r1), "=r"(r2), "=r"(r3) : "r"(a));
}
__device__ __forceinline__ uint32_t pack2h(float v0, float v1) {
    __half h0 = __float2half_rn(v0);
    __half h1 = __float2half_rn(v1);
    return (uint32_t)__half_as_ushort(h0) | ((uint32_t)__half_as_ushort(h1) << 16);
}

// prep: hi fp16 codebook (scaled), esq, max hi/lo norms. one warp per code.
__global__ void prep_kernel(const float* __restrict__ emb) {
    int warp = (blockIdx.x * blockDim.x + threadIdx.x) >> 5;
    int lane = threadIdx.x & 31;
    if (warp >= NCODES) return;
    const float* row = emb + (size_t)warp * CDIM;
    float v0 = row[lane] * SCALE, v1 = row[lane + 32] * SCALE;
    __half h0 = __float2half_rn(v0), h1 = __float2half_rn(v1);
    g_embh[warp * CDIM + lane]      = h0;
    g_embh[warp * CDIM + lane + 32] = h1;
    float hf0 = __half2float(h0), hf1 = __half2float(h1);
    float l0 = v0 - hf0, l1 = v1 - hf1;
    float s  = v0 * v0 + v1 * v1;
    float hs = hf0 * hf0 + hf1 * hf1;
    float ls = l0 * l0 + l1 * l1;
    #pragma unroll
    for (int off = 16; off; off >>= 1) {
        s  += __shfl_xor_sync(0xffffffffu, s,  off);
        hs += __shfl_xor_sync(0xffffffffu, hs, off);
        ls += __shfl_xor_sync(0xffffffffu, ls, off);
    }
    if (lane == 0) {
        g_esq[warp] = s;
        atomicMax(&g_Eh2, __float_as_int(hs));   // positive floats: int order = float order
        atomicMax(&g_El2, __float_as_int(ls));
    }
}

// ---- stage 1: 1-pass hi*hi GEMM, per-group min -> g_smin ----
__global__ __launch_bounds__(THREADS, 3)
void vq_main(const float* __restrict__ z) {
    extern __shared__ char sm[];
    const uint32_t sb = smem_u32(sm);
    const int tid  = threadIdx.x;
    const int lane = tid & 31;
    const int wid  = tid >> 5;      // 0..7 : token rows wid*16 + {grp, grp+8}
    const int grp  = lane >> 2;
    const int tid4 = lane & 3;

    const int n0  = blockIdx.x * M_TILE;
    const int bb  = n0 >> 12;
    const int hw0 = n0 & (HW - 1);
    const float* zb = z + (size_t)bb * CDIM * HW + hw0;

    const uint32_t bh_off[2] = { OFF_BH0, OFF_BH1 };

    // prologue: cp.async chunk 0 (hi + esq tail)
    {
        #pragma unroll
        for (int t = 0; t < 4; t++) {
            int item = tid + 256 * t;          // 0..1023
            int row  = item >> 3;
            int part = item & 7;
            cp16(sb + OFF_BH0 + row * B_STRIDE + part * 16, g_embh + row * 64 + part * 8);
        }
        if (tid < 32)
            cp16(sb + OFF_BH0 + ESQ_TAIL + tid * 16, g_esq + tid * 4);
        cp_commit();
    }

    // stage z (scaled, hi only) into A tile
    #pragma unroll
    for (int t = 0; t < 16; t++) {
        int i   = tid + 256 * t;
        int c2  = (i >> 7) * 2;
        int tok = i & 127;
        float v0 = zb[(size_t)c2 * HW + tok] * SCALE;
        float v1 = zb[(size_t)(c2 + 1) * HW + tok] * SCALE;
        *(uint32_t*)(sm + OFF_AH + tok * B_STRIDE + c2 * 2) = pack2h(v0, v1);
    }
    cp_wait<0>();
    __syncthreads();

    // ldmatrix lane address pieces
    const int arow  = (lane & 7) + ((lane >> 3) & 1) * 8;
    const int akoff = ((lane >> 4) & 1) * 16;
    const int brow  = (lane & 7) + ((lane >> 4) & 1) * 8;
    const int bkoff = ((lane >> 3) & 1) * 16;

    // A fragments persistent in registers (chunk-invariant)
    uint32_t Ah[4][4];
    {
        const uint32_t ahad = sb + OFF_AH + (uint32_t)(wid * 16 + arow) * B_STRIDE + akoff;
        #pragma unroll
        for (int s = 0; s < 4; s++)
            ldmx4(Ah[s][0], Ah[s][1], Ah[s][2], Ah[s][3], ahad + s * 32);
    }

    for (int ch = 0; ch < NCHUNKS; ch++) {
        const int buf = ch & 1;

        if (ch < NCHUNKS - 1) {
            const size_t cbase = (size_t)(ch + 1) * N_CHUNK * CDIM;
            #pragma unroll
            for (int t = 0; t < 4; t++) {
                int item = tid + 256 * t;
                int row  = item >> 3;
                int part = item & 7;
                cp16(sb + bh_off[buf ^ 1] + row * B_STRIDE + part * 16,
                     g_embh + cbase + row * 64 + part * 8);
            }
            if (tid < 32)
                cp16(sb + bh_off[buf ^ 1] + ESQ_TAIL + tid * 16,
                     g_esq + (ch + 1) * N_CHUNK + tid * 4);
            cp_commit();
            cp_wait<1>();
        } else {
            cp_wait<0>();
        }
        __syncthreads();

        const float* esq_t = (const float*)(sm + bh_off[buf] + ESQ_TAIL);

        #pragma unroll
        for (int step = 0; step < 4; step++) {
            const int nbase = step * 32;
            const uint32_t bhb = sb + bh_off[buf] + (uint32_t)(nbase + brow) * B_STRIDE + bkoff;

            float acc[4][4];
            #pragma unroll
            for (int f = 0; f < 4; f++)
                #pragma unroll
                for (int r = 0; r < 4; r++) acc[f][r] = 0.f;

            #pragma unroll
            for (int s = 0; s < 4; s++) {
                #pragma unroll
                for (int fp = 0; fp < 2; fp++) {
                    uint32_t h0, h1, h2, h3;
                    ldmx4(h0, h1, h2, h3, bhb + fp * (16 * B_STRIDE) + s * 32);
                    mma16816(acc[2 * fp],     Ah[s], h0, h1);
                    mma16816(acc[2 * fp + 1], Ah[s], h2, h3);
                }
            }

            // epilogue: 8-code group min -> smem submin buffer (descaled fp16)
            float2 ee[4];
            #pragma unroll
            for (int f = 0; f < 4; f++)
                ee[f] = *(const float2*)&esq_t[nbase + f * 8 + 2 * tid4];

            const int col = ((ch & 1) * 4 + step) * 4 + tid4;
            #pragma unroll
            for (int g = 0; g < 2; g++) {
                float sv[8];
                #pragma unroll
                for (int f = 0; f < 4; f++) {
                    sv[2 * f]     = fmaf(acc[f][g * 2 + 0], -2.0f, ee[f].x);
                    sv[2 * f + 1] = fmaf(acc[f][g * 2 + 1], -2.0f, ee[f].y);
                }
                float m01 = fminf(sv[0], sv[1]), m23 = fminf(sv[2], sv[3]);
                float m45 = fminf(sv[4], sv[5]), m67 = fminf(sv[6], sv[7]);
                float mn = fminf(fminf(m01, m23), fminf(m45, m67));
                int tok = wid * 16 + g * 8 + grp;
                *(__half*)(sm + OFF_SB + tok * 80 + col * 2) = __float2half_rn(mn * DESC);
            }
        }
        __syncthreads();

        if (ch & 1) {
            // dump 32 gids x 128 tokens to gmem, coalesced
            int tok = tid >> 1, hf = tid & 1;
            uint4 x0 = *(const uint4*)(sm + OFF_SB + tok * 80 + hf * 32);
            uint4 x1 = *(const uint4*)(sm + OFF_SB + tok * 80 + hf * 32 + 16);
            int base = (ch - 1) * 16;
            uint4* dp = (uint4*)(g_smin + (size_t)(n0 + tok) * 512 + base + hf * 16);
            dp[0] = x0;
            dp[1] = x1;
            __syncthreads();
        }
    }
}

// ---- stage 2: certified resolve + exact rescore + gather ----
__global__ __launch_bounds__(THREADS, 3)
void vq_resolve(const float* __restrict__ z,
                const float* __restrict__ emb,
                float* __restrict__ out) {
    extern __shared__ char sm[];
    float* zs    = (float*)sm;               // [64][130] natural z
    int*   sidx  = (int*)(sm + 33280);       // [128]
    float* eps_s = (float*)(sm + 33792);     // [128] per-token window (2*eps + slack)

    const int tid  = threadIdx.x;
    const int lane = tid & 31;
    const int wid  = tid >> 5;

    const int n0  = blockIdx.x * M_TILE;
    const int bb  = n0 >> 12;
    const int hw0 = n0 & (HW - 1);
    const float* zb = z + (size_t)bb * CDIM * HW + hw0;

    #pragma unroll
    for (int t = 0; t < 32; t++) {
        int i = tid + 256 * t;
        int c = i >> 7, tok = i & 127;
        zs[c * 130 + tok] = zb[(size_t)c * HW + tok];
    }
    __syncthreads();

    // prepass: per-token certified window, thread-per-token (no shfl chains)
    if (tid < 128) {
        const int t = tid;
        const float Eh2 = __int_as_float(g_Eh2);
        const float El2 = __int_as_float(g_El2);
        float hz = 0.f, lz = 0.f;
        #pragma unroll
        for (int c = 0; c < 64; c++) {
            float v = zs[c * 130 + t] * SCALE;
            float h = __half2float(__float2half_rn(v));
            float l = v - h;
            hz = fmaf(h, h, hz);
            lz = fmaf(l, l, lz);
        }
        float eps_dot = sqrtf(lz * Eh2) + sqrtf(hz * El2) + sqrtf(lz * El2);
        eps_s[t] = eps_dot * (4.0f * DESC) + 0.5f;   // 2*eps_dist*2x-margin + slack
    }
    __syncthreads();

    for (int tt = 0; tt < 16; tt++) {
        const int t  = wid * 16 + tt;
        const int tg = n0 + t;

        // load this token's 512 group mins (32B per lane)
        const uint4* sp = (const uint4*)(g_smin + (size_t)tg * 512);
        uint4 a = sp[lane * 2], b = sp[lane * 2 + 1];
        float hv[16];
        {
            uint32_t w[8] = { a.x, a.y, a.z, a.w, b.x, b.y, b.z, b.w };
            #pragma unroll
            for (int j = 0; j < 8; j++) {
                float2 f = __half22float2(*(__half2*)&w[j]);
                hv[2 * j] = f.x; hv[2 * j + 1] = f.y;
            }
        }
        float m = hv[0];
        #pragma unroll
        for (int j = 1; j < 16; j++) m = fminf(m, hv[j]);
        #pragma unroll
        for (int off = 16; off; off >>= 1)
            m = fminf(m, __shfl_xor_sync(0xffffffffu, m, off));

        const float thr = m + eps_s[t];

        float bv = FLT_MAX;
        int   bc = 0x7fffffff;
        const int kq = lane & 3;
        const int fsel = ((lane >> 3) << 3) + ((lane >> 2) & 1);  // f*8 + p

        #pragma unroll
        for (int i = 0; i < 16; i++) {
            unsigned mb = __ballot_sync(0xffffffffu, hv[i] <= thr);
            while (mb) {
                int src = __ffs(mb) - 1;
                mb &= mb - 1;
                int gid  = src * 16 + i;
                int code = (gid >> 2) * 32 + fsel + 2 * (gid & 3);
                // exact fp32 rescore: lane dots 16 dims
                const float4* e4 = (const float4*)(emb + (size_t)code * CDIM) + kq * 4;
                float dot = 0.f;
                #pragma unroll
                for (int j = 0; j < 4; j++) {
                    float4 e = __ldg(&e4[j]);
                    int k = kq * 16 + j * 4;
                    dot = fmaf(zs[(k + 0) * 130 + t], e.x, dot);
                    dot = fmaf(zs[(k + 1) * 130 + t], e.y, dot);
                    dot = fmaf(zs[(k + 2) * 130 + t], e.z, dot);
                    dot = fmaf(zs[(k + 3) * 130 + t], e.w, dot);
                }
                dot += __shfl_xor_sync(0xffffffffu, dot, 1);
                dot += __shfl_xor_sync(0xffffffffu, dot, 2);
                float d = fmaf(dot, -2.0f, g_esq[code] * DESC);
                int   c = code;
                #pragma unroll
                for (int off = 4; off <= 16; off <<= 1) {
                    float od = __shfl_xor_sync(0xffffffffu, d, off);
                    int   oc = __shfl_xor_sync(0xffffffffu, c, off);
                    if (od < d || (od == d && oc < c)) { d = od; c = oc; }
                }
                if (d < bv || (d == bv && c < bc)) { bv = d; bc = c; }
            }
        }
        if (lane == 0) sidx[t] = bc;
    }
    __syncthreads();

    // gather emb[idx], transposed coalesced write (stage over zs)
    float* st = zs;   // [128][65] = 33280 B, exact fit
    #pragma unroll
    for (int t = 0; t < 32; t++) {
        int i = tid + 256 * t;
        int tok = i >> 6, c = i & 63;
        st[tok * 65 + c] = emb[(size_t)sidx[tok] * CDIM + c];
    }
    __syncthreads();
    float* ob = out + (size_t)bb * CDIM * HW + hw0;
    #pragma unroll
    for (int t = 0; t < 32; t++) {
        int i = tid + 256 * t;
        int c = i >> 7, tok = i & 127;
        ob[(size_t)c * HW + tok] = st[tok * 65 + c];
    }
}

extern "C" void kernel_launch(void* const* d_in, const int* in_sizes, int n_in,
                              void* d_out, int out_size) {
    const float* z   = (const float*)d_in[0];
    const float* emb = (const float*)d_in[1];
    float* out = (float*)d_out;

    cudaFuncSetAttribute(vq_main, cudaFuncAttributeMaxDynamicSharedMemorySize, SMEM_MAIN);
    cudaFuncSetAttribute(vq_resolve, cudaFuncAttributeMaxDynamicSharedMemorySize, SMEM_RES);

    prep_kernel<<<NCODES / 8, 256>>>(emb);
    vq_main<<<NTOK / M_TILE, THREADS, SMEM_MAIN>>>(z);
    vq_resolve<<<NTOK / M_TILE, THREADS, SMEM_RES>>>(z, emb, out);
}

// round 16
// speedup vs baseline: 1.9271x; 1.0571x over previous
#include <cuda_runtime.h>
#include <cuda_fp16.h>
#include <float.h>
#include <stdint.h>

#define NCODES   4096
#define CDIM     64
#define NTOK     65536
#define HW       4096
#define M_TILE   128
#define N_CHUNK  256
#define NCHUNKS  16
#define THREADS  256
#define SCALE    64.0f
#define DESC     2.44140625e-4f   // 1/4096

#define B_STRIDE 144      // 64 halves (128B) + 16B pad -> conflict-free ldmatrix
#define ESQ_TAIL 36864    // esq tail offset inside each BH buffer (256 floats)

// ---- main kernel smem (per CTA 104448 -> 2 CTAs/SM) ----
#define OFF_AH     0        // 128*144 fp16 z-hi tile
#define OFF_BH0    18432    // 36864 data + 1024 esq
#define OFF_BH1    56320    // 36864 data + 1024 esq
#define OFF_SB     94208    // submin transpose buf: 128 tok x 40 halves = 10240
#define SMEM_MAIN  104448

// ---- resolve kernel smem ----
#define SMEM_RES   34304    // zs[64*130]f + sidx[128] + eps[128]

__device__ float  g_esq[NCODES];               // ||e*64||^2 (scaled by 4096)
__device__ __half g_embh[NCODES * CDIM];       // hi(e*64)
__device__ __half g_smin[(size_t)NTOK * 512];  // per (token, 8-code group) min, descaled
__device__ int    g_Eh2 = 0;                   // max_c ||hi_e||^2 (scaled), float bits
__device__ int    g_El2 = 0;                   // max_c ||lo_e||^2 (scaled), float bits

__device__ __forceinline__ uint32_t smem_u32(const void* p) {
    uint32_t a;
    asm("{ .reg .u64 t; cvta.to.shared.u64 t, %1; cvt.u32.u64 %0, t; }" : "=r"(a) : "l"(p));
    return a;
}
__device__ __forceinline__ void cp16(uint32_t dst, const void* src) {
    asm volatile("cp.async.cg.shared.global [%0], [%1], 16;" :: "r"(dst), "l"(src));
}
__device__ __forceinline__ void cp_commit() { asm volatile("cp.async.commit_group;"); }
template <int N>
__device__ __forceinline__ void cp_wait() { asm volatile("cp.async.wait_group %0;" :: "n"(N)); }

__device__ __forceinline__ void mma16816(float* c, const uint32_t* a, uint32_t b0, uint32_t b1) {
    asm volatile(
        "mma.sync.aligned.m16n8k16.row.col.f32.f16.f16.f32 "
        "{%0,%1,%2,%3}, {%4,%5,%6,%7}, {%8,%9}, {%0,%1,%2,%3};"
        : "+f"(c[0]), "+f"(c[1]), "+f"(c[2]), "+f"(c[3])
        : "r"(a[0]), "r"(a[1]), "r"(a[2]), "r"(a[3]), "r"(b0), "r"(b1));
}
__device__ __forceinline__ void ldmx4(uint32_t& r0, uint32_t& r1, uint32_t& r2, uint32_t& r3,
                                      uint32_t a) {
    asm volatile("ldmatrix.sync.aligned.m8n8.x4.shared.b16 {%0,%1,%2,%3}, [%4];"
        : "=r"(r0), "=r"(r1), "=r"(r2), "=r"(r3) : "r"(a));
}
__device__ __forceinline__ uint32_t pack2h(float v0, float v1) {
    __half h0 = __float2half_rn(v0);
    __half h1 = __float2half_rn(v1);
    return (uint32_t)__half_as_ushort(h0) | ((uint32_t)__half_as_ushort(h1) << 16);
}

// prep: hi fp16 codebook (scaled), esq, max hi/lo norms. one warp per code.
__global__ void prep_kernel(const float* __restrict__ emb) {
    int warp = (blockIdx.x * blockDim.x + threadIdx.x) >> 5;
    int lane = threadIdx.x & 31;
    if (warp >= NCODES) return;
    const float* row = emb + (size_t)warp * CDIM;
    float v0 = row[lane] * SCALE, v1 = row[lane + 32] * SCALE;
    __half h0 = __float2half_rn(v0), h1 = __float2half_rn(v1);
    g_embh[warp * CDIM + lane]      = h0;
    g_embh[warp * CDIM + lane + 32] = h1;
    float hf0 = __half2float(h0), hf1 = __half2float(h1);
    float l0 = v0 - hf0, l1 = v1 - hf1;
    float s  = v0 * v0 + v1 * v1;
    float hs = hf0 * hf0 + hf1 * hf1;
    float ls = l0 * l0 + l1 * l1;
    #pragma unroll
    for (int off = 16; off; off >>= 1) {
        s  += __shfl_xor_sync(0xffffffffu, s,  off);
        hs += __shfl_xor_sync(0xffffffffu, hs, off);
        ls += __shfl_xor_sync(0xffffffffu, ls, off);
    }
    if (lane == 0) {
        g_esq[warp] = s;
        atomicMax(&g_Eh2, __float_as_int(hs));   // positive floats: int order = float order
        atomicMax(&g_El2, __float_as_int(ls));
    }
}

// ---- stage 1: 1-pass hi*hi GEMM (m32 warp tile, 1:4 LDSM:MMA), group mins -> g_smin ----
__global__ __launch_bounds__(THREADS, 2)
void vq_main(const float* __restrict__ z) {
    extern __shared__ char sm[];
    const uint32_t sb = smem_u32(sm);
    const int tid  = threadIdx.x;
    const int lane = tid & 31;
    const int wid  = tid >> 5;
    const int grp  = lane >> 2;     // 0..7
    const int tid4 = lane & 3;      // 0..3
    const int mg   = wid >> 1;      // 0..3 : token rows mg*32 .. +31
    const int nw   = wid & 1;       // 0..1 : code cols nw*128 within 256-chunk

    const int n0  = blockIdx.x * M_TILE;
    const int bb  = n0 >> 12;
    const int hw0 = n0 & (HW - 1);
    const float* zb = z + (size_t)bb * CDIM * HW + hw0;

    const uint32_t bh_off[2] = { OFF_BH0, OFF_BH1 };

    // prologue: cp.async chunk 0 (hi + esq tail)
    {
        #pragma unroll
        for (int t = 0; t < 8; t++) {
            int item = tid + 256 * t;          // 0..2047
            int row  = item >> 3;
            int part = item & 7;
            cp16(sb + OFF_BH0 + row * B_STRIDE + part * 16, g_embh + row * 64 + part * 8);
        }
        if (tid < 64)
            cp16(sb + OFF_BH0 + ESQ_TAIL + tid * 16, g_esq + tid * 4);
        cp_commit();
    }

    // stage z (scaled, hi only) into A tile
    #pragma unroll
    for (int t = 0; t < 16; t++) {
        int i   = tid + 256 * t;
        int c2  = (i >> 7) * 2;
        int tok = i & 127;
        float v0 = zb[(size_t)c2 * HW + tok] * SCALE;
        float v1 = zb[(size_t)(c2 + 1) * HW + tok] * SCALE;
        *(uint32_t*)(sm + OFF_AH + tok * B_STRIDE + c2 * 2) = pack2h(v0, v1);
    }
    cp_wait<0>();
    __syncthreads();

    // ldmatrix lane address pieces
    const int arow  = (lane & 7) + ((lane >> 3) & 1) * 8;
    const int akoff = ((lane >> 4) & 1) * 16;
    const int brow  = (lane & 7) + ((lane >> 4) & 1) * 8;
    const int bkoff = ((lane >> 3) & 1) * 16;

    // A fragments persistent in registers: two m16 tiles (m32 total), tile-invariant
    uint32_t Ah[2][4][4];
    {
        const uint32_t ahad = sb + OFF_AH + (uint32_t)(mg * 32 + arow) * B_STRIDE + akoff;
        #pragma unroll
        for (int s = 0; s < 4; s++) {
            ldmx4(Ah[0][s][0], Ah[0][s][1], Ah[0][s][2], Ah[0][s][3], ahad + s * 32);
            ldmx4(Ah[1][s][0], Ah[1][s][1], Ah[1][s][2], Ah[1][s][3],
                  ahad + 16 * B_STRIDE + s * 32);
        }
    }

    for (int ch = 0; ch < NCHUNKS; ch++) {
        const int buf = ch & 1;

        if (ch < NCHUNKS - 1) {
            const size_t cbase = (size_t)(ch + 1) * N_CHUNK * CDIM;
            #pragma unroll
            for (int t = 0; t < 8; t++) {
                int item = tid + 256 * t;
                int row  = item >> 3;
                int part = item & 7;
                cp16(sb + bh_off[buf ^ 1] + row * B_STRIDE + part * 16,
                     g_embh + cbase + row * 64 + part * 8);
            }
            if (tid < 64)
                cp16(sb + bh_off[buf ^ 1] + ESQ_TAIL + tid * 16,
                     g_esq + (ch + 1) * N_CHUNK + tid * 4);
            cp_commit();
            cp_wait<1>();
        } else {
            cp_wait<0>();
        }
        __syncthreads();

        const float* esq_t = (const float*)(sm + bh_off[buf] + ESQ_TAIL);

        // ---- 4 n32 steps over this warp's 128-code half ----
        #pragma unroll
        for (int step = 0; step < 4; step++) {
            const int nbase = nw * 128 + step * 32;
            const uint32_t bhb = sb + bh_off[buf] + (uint32_t)(nbase + brow) * B_STRIDE + bkoff;

            float acc[2][4][4];
            #pragma unroll
            for (int m = 0; m < 2; m++)
                #pragma unroll
                for (int f = 0; f < 4; f++)
                    #pragma unroll
                    for (int r = 0; r < 4; r++) acc[m][f][r] = 0.f;

            #pragma unroll
            for (int s = 0; s < 4; s++) {
                uint32_t h0, h1, h2, h3, h4, h5, h6, h7;
                ldmx4(h0, h1, h2, h3, bhb + s * 32);
                ldmx4(h4, h5, h6, h7, bhb + 16 * B_STRIDE + s * 32);
                mma16816(acc[0][0], Ah[0][s], h0, h1);
                mma16816(acc[0][1], Ah[0][s], h2, h3);
                mma16816(acc[1][0], Ah[1][s], h0, h1);
                mma16816(acc[1][1], Ah[1][s], h2, h3);
                mma16816(acc[0][2], Ah[0][s], h4, h5);
                mma16816(acc[0][3], Ah[0][s], h6, h7);
                mma16816(acc[1][2], Ah[1][s], h4, h5);
                mma16816(acc[1][3], Ah[1][s], h6, h7);
            }

            // epilogue: 8-code group min -> smem submin buffer (descaled fp16)
            float2 ee[4];
            #pragma unroll
            for (int f = 0; f < 4; f++)
                ee[f] = *(const float2*)&esq_t[nbase + f * 8 + 2 * tid4];

            const int col = (nw * 4 + step) * 4 + tid4;
            #pragma unroll
            for (int g = 0; g < 4; g++) {   // token = mg*32 + (g>>1)*16 + (g&1)*8 + grp
                const int m = g >> 1, h = g & 1;
                float sv[8];
                #pragma unroll
                for (int f = 0; f < 4; f++) {
                    sv[2 * f]     = fmaf(acc[m][f][h * 2 + 0], -2.0f, ee[f].x);
                    sv[2 * f + 1] = fmaf(acc[m][f][h * 2 + 1], -2.0f, ee[f].y);
                }
                float m01 = fminf(sv[0], sv[1]), m23 = fminf(sv[2], sv[3]);
                float m45 = fminf(sv[4], sv[5]), m67 = fminf(sv[6], sv[7]);
                float mn = fminf(fminf(m01, m23), fminf(m45, m67));
                int tok = mg * 32 + m * 16 + h * 8 + grp;
                *(__half*)(sm + OFF_SB + tok * 80 + col * 2) = __float2half_rn(mn * DESC);
            }
        }
        __syncthreads();

        // dump 32 gid-cols x 128 tokens to gmem, coalesced
        {
            int tok = tid >> 1, hf = tid & 1;
            uint4 x0 = *(const uint4*)(sm + OFF_SB + tok * 80 + hf * 32);
            uint4 x1 = *(const uint4*)(sm + OFF_SB + tok * 80 + hf * 32 + 16);
            uint4* dp = (uint4*)(g_smin + (size_t)(n0 + tok) * 512 + ch * 32 + hf * 16);
            dp[0] = x0;
            dp[1] = x1;
        }
        __syncthreads();
    }
}

// ---- stage 2: certified resolve + exact rescore + gather (unchanged from R15) ----
__global__ __launch_bounds__(THREADS, 3)
void vq_resolve(const float* __restrict__ z,
                const float* __restrict__ emb,
                float* __restrict__ out) {
    extern __shared__ char sm[];
    float* zs    = (float*)sm;               // [64][130] natural z
    int*   sidx  = (int*)(sm + 33280);       // [128]
    float* eps_s = (float*)(sm + 33792);     // [128] per-token window

    const int tid  = threadIdx.x;
    const int lane = tid & 31;
    const int wid  = tid >> 5;

    const int n0  = blockIdx.x * M_TILE;
    const int bb  = n0 >> 12;
    const int hw0 = n0 & (HW - 1);
    const float* zb = z + (size_t)bb * CDIM * HW + hw0;

    #pragma unroll
    for (int t = 0; t < 32; t++) {
        int i = tid + 256 * t;
        int c = i >> 7, tok = i & 127;
        zs[c * 130 + tok] = zb[(size_t)c * HW + tok];
    }
    __syncthreads();

    // prepass: per-token certified window, thread-per-token
    if (tid < 128) {
        const int t = tid;
        const float Eh2 = __int_as_float(g_Eh2);
        const float El2 = __int_as_float(g_El2);
        float hz = 0.f, lz = 0.f;
        #pragma unroll
        for (int c = 0; c < 64; c++) {
            float v = zs[c * 130 + t] * SCALE;
            float h = __half2float(__float2half_rn(v));
            float l = v - h;
            hz = fmaf(h, h, hz);
            lz = fmaf(l, l, lz);
        }
        float eps_dot = sqrtf(lz * Eh2) + sqrtf(hz * El2) + sqrtf(lz * El2);
        eps_s[t] = eps_dot * (4.0f * DESC) + 0.5f;
    }
    __syncthreads();

    for (int tt = 0; tt < 16; tt++) {
        const int t  = wid * 16 + tt;
        const int tg = n0 + t;

        const uint4* sp = (const uint4*)(g_smin + (size_t)tg * 512);
        uint4 a = sp[lane * 2], b = sp[lane * 2 + 1];
        float hv[16];
        {
            uint32_t w[8] = { a.x, a.y, a.z, a.w, b.x, b.y, b.z, b.w };
            #pragma unroll
            for (int j = 0; j < 8; j++) {
                float2 f = __half22float2(*(__half2*)&w[j]);
                hv[2 * j] = f.x; hv[2 * j + 1] = f.y;
            }
        }
        float m = hv[0];
        #pragma unroll
        for (int j = 1; j < 16; j++) m = fminf(m, hv[j]);
        #pragma unroll
        for (int off = 16; off; off >>= 1)
            m = fminf(m, __shfl_xor_sync(0xffffffffu, m, off));

        const float thr = m + eps_s[t];

        float bv = FLT_MAX;
        int   bc = 0x7fffffff;
        const int kq = lane & 3;
        const int fsel = ((lane >> 3) << 3) + ((lane >> 2) & 1);  // f*8 + p

        #pragma unroll
        for (int i = 0; i < 16; i++) {
            unsigned mb = __ballot_sync(0xffffffffu, hv[i] <= thr);
            while (mb) {
                int src = __ffs(mb) - 1;
                mb &= mb - 1;
                int gid  = src * 16 + i;
                int code = (gid >> 2) * 32 + fsel + 2 * (gid & 3);
                const float4* e4 = (const float4*)(emb + (size_t)code * CDIM) + kq * 4;
                float dot = 0.f;
                #pragma unroll
                for (int j = 0; j < 4; j++) {
                    float4 e = __ldg(&e4[j]);
                    int k = kq * 16 + j * 4;
                    dot = fmaf(zs[(k + 0) * 130 + t], e.x, dot);
                    dot = fmaf(zs[(k + 1) * 130 + t], e.y, dot);
                    dot = fmaf(zs[(k + 2) * 130 + t], e.z, dot);
                    dot = fmaf(zs[(k + 3) * 130 + t], e.w, dot);
                }
                dot += __shfl_xor_sync(0xffffffffu, dot, 1);
                dot += __shfl_xor_sync(0xffffffffu, dot, 2);
                float d = fmaf(dot, -2.0f, g_esq[code] * DESC);
                int   c = code;
                #pragma unroll
                for (int off = 4; off <= 16; off <<= 1) {
                    float od = __shfl_xor_sync(0xffffffffu, d, off);
                    int   oc = __shfl_xor_sync(0xffffffffu, c, off);
                    if (od < d || (od == d && oc < c)) { d = od; c = oc; }
                }
                if (d < bv || (d == bv && c < bc)) { bv = d; bc = c; }
            }
        }
        if (lane == 0) sidx[t] = bc;
    }
    __syncthreads();

    // gather emb[idx], transposed coalesced write (stage over zs)
    float* st = zs;   // [128][65]
    #pragma unroll
    for (int t = 0; t < 32; t++) {
        int i = tid + 256 * t;
        int tok = i >> 6, c = i & 63;
        st[tok * 65 + c] = emb[(size_t)sidx[tok] * CDIM + c];
    }
    __syncthreads();
    float* ob = out + (size_t)bb * CDIM * HW + hw0;
    #pragma unroll
    for (int t = 0; t < 32; t++) {
        int i = tid + 256 * t;
        int c = i >> 7, tok = i & 127;
        ob[(size_t)c * HW + tok] = st[tok * 65 + c];
    }
}

extern "C" void kernel_launch(void* const* d_in, const int* in_sizes, int n_in,
                              void* d_out, int out_size) {
    const float* z   = (const float*)d_in[0];
    const float* emb = (const float*)d_in[1];
    float* out = (float*)d_out;

    cudaFuncSetAttribute(vq_main, cudaFuncAttributeMaxDynamicSharedMemorySize, SMEM_MAIN);
    cudaFuncSetAttribute(vq_resolve, cudaFuncAttributeMaxDynamicSharedMemorySize, SMEM_RES);

    prep_kernel<<<NCODES / 8, 256>>>(emb);
    vq_main<<<NTOK / M_TILE, THREADS, SMEM_MAIN>>>(z);
    vq_resolve<<<NTOK / M_TILE, THREADS, SMEM_RES>>>(z, emb, out);
}